// round 3
// baseline (speedup 1.0000x reference)
#include <cuda_runtime.h>
#include <math.h>

// Problem shape (fixed by setup_inputs)
#define Bb   32
#define Hh   64
#define Ww   48
#define Cc   256
#define Dd   32
#define BG   256            // Bb * groups(8)
#define NPIX (Hh*Ww)        // 3072
#define LN_EPS 1e-3f
#define NCHUNK 6            // pass3 blocks per bg

// Scratch (device globals — no allocation allowed)
__device__ float g_rowmean[BG*Hh*Dd];
__device__ float g_colmean[BG*Ww*Dd];
__device__ float g_xh[BG*Hh*Dd];
__device__ float g_xw[BG*Ww*Dd];
__device__ float g_Apart[BG*NCHUNK*Dd];
__device__ float g_Bpart[BG*NCHUNK];
__device__ float g_c[BG*Dd];       // x21 * gamma
__device__ float g_csum[BG];       // sum(x21*gamma)
__device__ float g_cb[BG];         // dot(x21, beta)
__device__ float g_weff[BG*9*Dd];  // x11-projected conv3x3 kernel
__device__ float g_beff[BG];       // dot(x11, conv3x3_b)

__device__ __forceinline__ float wsum(float v){
#pragma unroll
    for (int o = 16; o; o >>= 1) v += __shfl_xor_sync(0xffffffffu, v, o);
    return v;
}
__device__ __forceinline__ float wmax(float v){
#pragma unroll
    for (int o = 16; o; o >>= 1) v = fmaxf(v, __shfl_xor_sync(0xffffffffu, v, o));
    return v;
}

// ---------------------------------------------------------------------------
// Pass 1: per-(bg) row means [H,d] and col means [W,d]. One block per bg.
// ---------------------------------------------------------------------------
__global__ void pass1(const float* __restrict__ x)
{
    int bg = blockIdx.x;
    int b = bg >> 3, gi = bg & 7;
    int lane = threadIdx.x & 31, warp = threadIdx.x >> 5;   // 16 warps
    const float* xb = x + ((size_t)b*Hh)*Ww*Cc + gi*Dd + lane;

    // row means: warp handles rows warp, warp+16, ...
    for (int h = warp; h < Hh; h += 16) {
        float s = 0.f;
        const float* rp = xb + (size_t)h*Ww*Cc;
        for (int w = 0; w < Ww; ++w) s += rp[(size_t)w*Cc];
        g_rowmean[(bg*Hh + h)*Dd + lane] = s * (1.0f/Ww);
    }
    // col means
    for (int w = warp; w < Ww; w += 16) {
        float s = 0.f;
        const float* cp = xb + (size_t)w*Cc;
        for (int h = 0; h < Hh; ++h) s += cp[(size_t)h*Ww*Cc];
        g_colmean[(bg*Ww + w)*Dd + lane] = s * (1.0f/Hh);
    }
}

// ---------------------------------------------------------------------------
// Pass 2: conv1x1+sigmoid gates (xh, xw); analytic mean(x2) -> softmax -> x21,
// plus c = x21*gamma, csum, cb. One block (128 thr) per bg.
// ---------------------------------------------------------------------------
__global__ void pass2(const float* __restrict__ x,
                      const float* __restrict__ w1x1,
                      const float* __restrict__ b1,
                      const float* __restrict__ w3,
                      const float* __restrict__ b3,
                      const float* __restrict__ gamma,
                      const float* __restrict__ beta)
{
    __shared__ float smW[Dd*Dd];
    __shared__ float smS[9*Dd];
    int bg = blockIdx.x;
    int b = bg >> 3, gi = bg & 7;
    int tid = threadIdx.x;
    int lane = tid & 31, warp = tid >> 5;   // 4 warps

    for (int i = tid; i < Dd*Dd; i += blockDim.x) smW[i] = w1x1[i];
    __syncthreads();

    float bias = b1[lane];
    for (int p = warp; p < Hh + Ww; p += 4) {
        float v = (p < Hh) ? g_rowmean[(bg*Hh + p)*Dd + lane]
                           : g_colmean[(bg*Ww + (p - Hh))*Dd + lane];
        float acc = bias;
#pragma unroll
        for (int i = 0; i < Dd; ++i) {
            float vi = __shfl_sync(0xffffffffu, v, i);
            acc += vi * smW[i*Dd + lane];
        }
        float s = 1.f/(1.f + expf(-acc));
        if (p < Hh) g_xh[(bg*Hh + p)*Dd + lane] = s;
        else        g_xw[(bg*Ww + (p - Hh))*Dd + lane] = s;
    }

    if (warp == 0) {
        int i = lane;
        // region sums for SAME 3x3 conv mean
        float T = 0.f;
        for (int h = 0; h < Hh; ++h) T += g_rowmean[(bg*Hh + h)*Dd + i];
        T *= (float)Ww;
        float R0 = g_rowmean[(bg*Hh + 0     )*Dd + i] * (float)Ww;
        float RL = g_rowmean[(bg*Hh + Hh - 1)*Dd + i] * (float)Ww;
        float C0 = g_colmean[(bg*Ww + 0     )*Dd + i] * (float)Hh;
        float CL = g_colmean[(bg*Ww + Ww - 1)*Dd + i] * (float)Hh;
        const float* xb = x + ((size_t)b*Hh)*Ww*Cc + gi*Dd + i;
        float ctl = xb[0];
        float ctr = xb[(size_t)(Ww-1)*Cc];
        float cbl = xb[((size_t)(Hh-1)*Ww)*Cc];
        float cbr = xb[((size_t)(Hh-1)*Ww + (Ww-1))*Cc];
#pragma unroll
        for (int dy = -1; dy <= 1; ++dy) {
#pragma unroll
            for (int dx = -1; dx <= 1; ++dx) {
                float eR = (dy == -1) ? RL : (dy == 1) ? R0 : 0.f;
                float eC = (dx == -1) ? CL : (dx == 1) ? C0 : 0.f;
                float corner = 0.f;
                if (dy == -1 && dx == -1) corner = cbr;
                if (dy == -1 && dx ==  1) corner = cbl;
                if (dy ==  1 && dx == -1) corner = ctr;
                if (dy ==  1 && dx ==  1) corner = ctl;
                smS[((dy+1)*3 + (dx+1))*Dd + i] = T - eR - eC + corner;
            }
        }
        __syncwarp();
        int e = lane;
        float acc = 0.f;
        for (int k = 0; k < 9; ++k) {
#pragma unroll
            for (int ii = 0; ii < Dd; ++ii)
                acc += w3[(k*Dd + ii)*Dd + e] * smS[k*Dd + ii];
        }
        float m2 = acc * (1.f/NPIX) + b3[e];
        float mx = wmax(m2);
        float pz = expf(m2 - mx);
        float ps = wsum(pz);
        float x21 = pz/ps;
        float cv = x21 * gamma[e];
        g_c[bg*Dd + e] = cv;
        float cs  = wsum(cv);
        float cbv = wsum(x21 * beta[e]);
        if (e == 0) { g_csum[bg] = cs; g_cb[bg] = cbv; }
    }
}

// ---------------------------------------------------------------------------
// Pass 3: streaming LN-stat reduction: A_e = sum rs*y_e, Bs = sum rs*mu.
// grid = BG*NCHUNK blocks, 512 threads (16 warps), warp = one pixel / step.
// ---------------------------------------------------------------------------
__global__ void pass3(const float* __restrict__ x)
{
    __shared__ float sA[16*Dd];
    __shared__ float sB[16];
    int bg = blockIdx.x / NCHUNK, chunk = blockIdx.x % NCHUNK;
    int b = bg >> 3, gi = bg & 7;
    int lane = threadIdx.x & 31, warp = threadIdx.x >> 5;
    const float* xb = x + ((size_t)b*Hh)*Ww*Cc + gi*Dd + lane;

    float accA = 0.f, accB = 0.f;
    int pix0 = chunk * 512;
#pragma unroll 4
    for (int j = 0; j < 32; ++j) {
        int p = pix0 + j*16 + warp;
        int h = p / Ww, w = p - h*Ww;
        float gx = xb[((size_t)h*Ww + w)*Cc];
        float y = gx * g_xh[(bg*Hh + h)*Dd + lane] * g_xw[(bg*Ww + w)*Dd + lane];
        float mu = wsum(y) * (1.f/Dd);
        float t = y - mu;
        float var = wsum(t*t) * (1.f/Dd);
        float rs = rsqrtf(var + LN_EPS);
        accA += rs * y;
        accB += rs * mu;
    }
    sA[warp*Dd + lane] = accA;
    if (lane == 0) sB[warp] = accB;
    __syncthreads();
    if (warp == 0) {
        float s = 0.f;
        for (int k = 0; k < 16; ++k) s += sA[k*Dd + lane];
        g_Apart[(bg*NCHUNK + chunk)*Dd + lane] = s;
        if (lane == 0) {
            float sb = 0.f;
            for (int k = 0; k < 16; ++k) sb += sB[k];
            g_Bpart[bg*NCHUNK + chunk] = sb;
        }
    }
}

// ---------------------------------------------------------------------------
// Pass 4: x11 = softmax(GAP(x1)); weff[k,i] = sum_e w3[k,i,e]*x11[e]; beff.
// One block (288 thr) per bg.
// ---------------------------------------------------------------------------
__global__ void pass4(const float* __restrict__ w3,
                      const float* __restrict__ b3,
                      const float* __restrict__ gamma,
                      const float* __restrict__ beta)
{
    __shared__ float x11sm[Dd];
    int bg = blockIdx.x;
    int tid = threadIdx.x;
    if (tid < 32) {
        int e = tid;
        float A = 0.f, Bs = 0.f;
        for (int c = 0; c < NCHUNK; ++c) {
            A  += g_Apart[(bg*NCHUNK + c)*Dd + e];
            Bs += g_Bpart[bg*NCHUNK + c];
        }
        float v = gamma[e] * (A - Bs) * (1.f/NPIX) + beta[e];
        float mx = wmax(v);
        float p = expf(v - mx);
        float ps = wsum(p);
        float x11 = p/ps;
        x11sm[e] = x11;
        float be = wsum(x11 * b3[e]);
        if (e == 0) g_beff[bg] = be;
    }
    __syncthreads();
    if (tid < 288) {
        int k = tid >> 5, i = tid & 31;
        float acc = 0.f;
#pragma unroll
        for (int e = 0; e < Dd; ++e) acc += w3[(k*Dd + i)*Dd + e] * x11sm[e];
        g_weff[(bg*9 + k)*Dd + i] = acc;
    }
}

// ---------------------------------------------------------------------------
// Pass 5: per pixel: w1 (projected 3x3 conv), recompute LN -> w2, gate, out.
// grid = BG*Hh (one block per pixel-row), 256 thr = 8 warps, warp = pixel.
// ---------------------------------------------------------------------------
__global__ void pass5(const float* __restrict__ x, float* __restrict__ out)
{
    int bg = blockIdx.x / Hh, h = blockIdx.x % Hh;
    int b = bg >> 3, gi = bg & 7;
    int lane = threadIdx.x & 31, warp = threadIdx.x >> 5;
    const float* xb = x + ((size_t)b*Hh)*Ww*Cc + gi*Dd + lane;
    float* ob = out + ((size_t)b*Hh)*Ww*Cc + gi*Dd + lane;

    float xhv  = g_xh[(bg*Hh + h)*Dd + lane];
    float cv   = g_c[bg*Dd + lane];
    float csum = g_csum[bg], cb = g_cb[bg], beff = g_beff[bg];
    float wk[9];
#pragma unroll
    for (int k = 0; k < 9; ++k) wk[k] = g_weff[(bg*9 + k)*Dd + lane];

    for (int w = warp; w < Ww; w += 8) {
        float conv = 0.f, gxc = 0.f;
#pragma unroll
        for (int dy = -1; dy <= 1; ++dy) {
            int hh = h + dy;
            if (hh < 0 || hh >= Hh) continue;
            const float* rp = xb + (size_t)hh*Ww*Cc;
#pragma unroll
            for (int dx = -1; dx <= 1; ++dx) {
                int ww = w + dx;
                if (ww < 0 || ww >= Ww) continue;
                float v = rp[(size_t)ww*Cc];
                conv += v * wk[(dy+1)*3 + (dx+1)];
                if (dy == 0 && dx == 0) gxc = v;
            }
        }
        float w1 = wsum(conv) + beff;
        float y  = gxc * xhv * g_xw[(bg*Ww + w)*Dd + lane];
        float mu = wsum(y) * (1.f/Dd);
        float t  = y - mu;
        float var = wsum(t*t) * (1.f/Dd);
        float rs  = rsqrtf(var + LN_EPS);
        float dotcy = wsum(cv * y);
        float w2 = rs * (dotcy - mu*csum) + cb;
        float gate = 1.f/(1.f + expf(-(w1 + w2)));
        ob[((size_t)h*Ww + w)*Cc] = gxc * gate;
    }
}

// ---------------------------------------------------------------------------
extern "C" void kernel_launch(void* const* d_in, const int* in_sizes, int n_in,
                              void* d_out, int out_size)
{
    const float* x   = (const float*)d_in[0];
    const float* w1  = (const float*)d_in[1];
    const float* b1  = (const float*)d_in[2];
    const float* w3  = (const float*)d_in[3];
    const float* b3  = (const float*)d_in[4];
    const float* gm  = (const float*)d_in[5];
    const float* bt  = (const float*)d_in[6];
    float* out = (float*)d_out;

    pass1<<<BG, 512>>>(x);
    pass2<<<BG, 128>>>(x, w1, b1, w3, b3, gm, bt);
    pass3<<<BG*NCHUNK, 512>>>(x);
    pass4<<<BG, 288>>>(w3, b3, gm, bt);
    pass5<<<BG*Hh, 256>>>(x, out);
}

// round 4
// speedup vs baseline: 1.0076x; 1.0076x over previous
#include <cuda_runtime.h>
#include <math.h>

// Problem shape (fixed by setup_inputs)
#define Bb   32
#define Hh   64
#define Ww   48
#define Cc   256
#define Dd   32
#define BG   256            // Bb * groups(8)
#define NPIX (Hh*Ww)        // 3072
#define LN_EPS 1e-3f
#define NCHUNK 6            // pass3 blocks per bg

// Scratch (device globals — no allocation allowed)
__device__ float g_rowmean[BG*Hh*Dd];
__device__ float g_colmean[BG*Ww*Dd];
__device__ float g_xh[BG*Hh*Dd];
__device__ float g_xw[BG*Ww*Dd];
__device__ float g_Apart[BG*NCHUNK*Dd];
__device__ float g_Bpart[BG*NCHUNK];
__device__ float g_c[BG*Dd];       // x21 * gamma
__device__ float g_csum[BG];       // sum(x21*gamma)
__device__ float g_cb[BG];         // dot(x21, beta)
__device__ float g_weff[BG*9*Dd];  // x11-projected conv3x3 kernel
__device__ float g_beff[BG];       // dot(x11, conv3x3_b)

__device__ __forceinline__ float wsum(float v){
#pragma unroll
    for (int o = 16; o; o >>= 1) v += __shfl_xor_sync(0xffffffffu, v, o);
    return v;
}
__device__ __forceinline__ float wmax(float v){
#pragma unroll
    for (int o = 16; o; o >>= 1) v = fmaxf(v, __shfl_xor_sync(0xffffffffu, v, o));
    return v;
}

// ---------------------------------------------------------------------------
// Pass 1: single sweep of x -> row means and col means.
// 256 thr = 8 warps; warp handles 8 rows; col partials staged in 48KB smem.
// ---------------------------------------------------------------------------
__global__ void pass1(const float* __restrict__ x)
{
    __shared__ float colpart[8][Ww][Dd];   // 48 KB exactly
    int bg = blockIdx.x;
    int b = bg >> 3, gi = bg & 7;
    int lane = threadIdx.x & 31, warp = threadIdx.x >> 5;   // 8 warps
    const float* xb = x + ((size_t)b*Hh)*Ww*Cc + gi*Dd + lane;
    int r0 = warp * 8;

    float rowacc[8];
#pragma unroll
    for (int r = 0; r < 8; ++r) rowacc[r] = 0.f;

#pragma unroll 2
    for (int w = 0; w < Ww; ++w) {
        float cacc = 0.f;
#pragma unroll
        for (int r = 0; r < 8; ++r) {
            float v = xb[((size_t)(r0 + r)*Ww + w)*Cc];
            rowacc[r] += v;
            cacc += v;
        }
        colpart[warp][w][lane] = cacc;
    }
#pragma unroll
    for (int r = 0; r < 8; ++r)
        g_rowmean[(bg*Hh + r0 + r)*Dd + lane] = rowacc[r] * (1.0f/Ww);

    __syncthreads();
    for (int t = threadIdx.x; t < Ww*Dd; t += blockDim.x) {
        int w = t >> 5, ch = t & 31;
        float s = 0.f;
#pragma unroll
        for (int sp = 0; sp < 8; ++sp) s += colpart[sp][w][ch];
        g_colmean[(bg*Ww + w)*Dd + ch] = s * (1.0f/Hh);
    }
}

// ---------------------------------------------------------------------------
// Pass 2: conv1x1+sigmoid gates (xh, xw); analytic mean(x2) -> softmax -> x21,
// plus c = x21*gamma, csum, cb. One block (128 thr) per bg.
// ---------------------------------------------------------------------------
__global__ void pass2(const float* __restrict__ x,
                      const float* __restrict__ w1x1,
                      const float* __restrict__ b1,
                      const float* __restrict__ w3,
                      const float* __restrict__ b3,
                      const float* __restrict__ gamma,
                      const float* __restrict__ beta)
{
    __shared__ float smW[Dd*Dd];
    __shared__ float smS[9*Dd];
    int bg = blockIdx.x;
    int b = bg >> 3, gi = bg & 7;
    int tid = threadIdx.x;
    int lane = tid & 31, warp = tid >> 5;   // 4 warps

    for (int i = tid; i < Dd*Dd; i += blockDim.x) smW[i] = w1x1[i];
    __syncthreads();

    float bias = b1[lane];
    for (int p = warp; p < Hh + Ww; p += 4) {
        float v = (p < Hh) ? g_rowmean[(bg*Hh + p)*Dd + lane]
                           : g_colmean[(bg*Ww + (p - Hh))*Dd + lane];
        float acc = bias;
#pragma unroll
        for (int i = 0; i < Dd; ++i) {
            float vi = __shfl_sync(0xffffffffu, v, i);
            acc += vi * smW[i*Dd + lane];
        }
        float s = 1.f/(1.f + expf(-acc));
        if (p < Hh) g_xh[(bg*Hh + p)*Dd + lane] = s;
        else        g_xw[(bg*Ww + (p - Hh))*Dd + lane] = s;
    }

    if (warp == 0) {
        int i = lane;
        // region sums for SAME 3x3 conv mean
        float T = 0.f;
        for (int h = 0; h < Hh; ++h) T += g_rowmean[(bg*Hh + h)*Dd + i];
        T *= (float)Ww;
        float R0 = g_rowmean[(bg*Hh + 0     )*Dd + i] * (float)Ww;
        float RL = g_rowmean[(bg*Hh + Hh - 1)*Dd + i] * (float)Ww;
        float C0 = g_colmean[(bg*Ww + 0     )*Dd + i] * (float)Hh;
        float CL = g_colmean[(bg*Ww + Ww - 1)*Dd + i] * (float)Hh;
        const float* xb = x + ((size_t)b*Hh)*Ww*Cc + gi*Dd + i;
        float ctl = xb[0];
        float ctr = xb[(size_t)(Ww-1)*Cc];
        float cbl = xb[((size_t)(Hh-1)*Ww)*Cc];
        float cbr = xb[((size_t)(Hh-1)*Ww + (Ww-1))*Cc];
#pragma unroll
        for (int dy = -1; dy <= 1; ++dy) {
#pragma unroll
            for (int dx = -1; dx <= 1; ++dx) {
                float eR = (dy == -1) ? RL : (dy == 1) ? R0 : 0.f;
                float eC = (dx == -1) ? CL : (dx == 1) ? C0 : 0.f;
                float corner = 0.f;
                if (dy == -1 && dx == -1) corner = cbr;
                if (dy == -1 && dx ==  1) corner = cbl;
                if (dy ==  1 && dx == -1) corner = ctr;
                if (dy ==  1 && dx ==  1) corner = ctl;
                smS[((dy+1)*3 + (dx+1))*Dd + i] = T - eR - eC + corner;
            }
        }
        __syncwarp();
        int e = lane;
        float acc = 0.f;
        for (int k = 0; k < 9; ++k) {
#pragma unroll
            for (int ii = 0; ii < Dd; ++ii)
                acc += w3[(k*Dd + ii)*Dd + e] * smS[k*Dd + ii];
        }
        float m2 = acc * (1.f/NPIX) + b3[e];
        float mx = wmax(m2);
        float pz = expf(m2 - mx);
        float ps = wsum(pz);
        float x21 = pz/ps;
        float cv = x21 * gamma[e];
        g_c[bg*Dd + e] = cv;
        float cs  = wsum(cv);
        float cbv = wsum(x21 * beta[e]);
        if (e == 0) { g_csum[bg] = cs; g_cb[bg] = cbv; }
    }
}

// ---------------------------------------------------------------------------
// Pass 3: streaming LN-stat reduction: A_e = sum rs*y_e, Bs = sum rs*mu.
// 2 pixels per iteration, 4 independent interleaved butterflies.
// ---------------------------------------------------------------------------
__global__ void pass3(const float* __restrict__ x)
{
    __shared__ float sA[16*Dd];
    __shared__ float sB[16];
    int bg = blockIdx.x / NCHUNK, chunk = blockIdx.x % NCHUNK;
    int b = bg >> 3, gi = bg & 7;
    int lane = threadIdx.x & 31, warp = threadIdx.x >> 5;  // 16 warps
    const float* xb = x + ((size_t)b*Hh)*Ww*Cc + gi*Dd + lane;

    float accA = 0.f, accB = 0.f;
    int pix0 = chunk * 512;
#pragma unroll 2
    for (int j = 0; j < 16; ++j) {
        int p  = pix0 + j*32 + warp;
        int q  = p + 16;
        int h1 = p / Ww, w1 = p - h1*Ww;
        int h2 = q / Ww, w2 = q - h2*Ww;
        float gx1 = xb[((size_t)h1*Ww + w1)*Cc];
        float gx2 = xb[((size_t)h2*Ww + w2)*Cc];
        float y1 = gx1 * g_xh[(bg*Hh + h1)*Dd + lane] * g_xw[(bg*Ww + w1)*Dd + lane];
        float y2 = gx2 * g_xh[(bg*Hh + h2)*Dd + lane] * g_xw[(bg*Ww + w2)*Dd + lane];
        float s1 = y1, s2 = y1*y1, s3 = y2, s4 = y2*y2;
#pragma unroll
        for (int o = 16; o; o >>= 1) {
            s1 += __shfl_xor_sync(0xffffffffu, s1, o);
            s2 += __shfl_xor_sync(0xffffffffu, s2, o);
            s3 += __shfl_xor_sync(0xffffffffu, s3, o);
            s4 += __shfl_xor_sync(0xffffffffu, s4, o);
        }
        float mu1 = s1*(1.f/Dd), var1 = s2*(1.f/Dd) - mu1*mu1;
        float mu2 = s3*(1.f/Dd), var2 = s4*(1.f/Dd) - mu2*mu2;
        float rs1 = rsqrtf(var1 + LN_EPS);
        float rs2 = rsqrtf(var2 + LN_EPS);
        accA += rs1*y1 + rs2*y2;
        accB += rs1*mu1 + rs2*mu2;
    }
    sA[warp*Dd + lane] = accA;
    if (lane == 0) sB[warp] = accB;
    __syncthreads();
    if (warp == 0) {
        float s = 0.f;
        for (int k = 0; k < 16; ++k) s += sA[k*Dd + lane];
        g_Apart[(bg*NCHUNK + chunk)*Dd + lane] = s;
        if (lane == 0) {
            float sb = 0.f;
            for (int k = 0; k < 16; ++k) sb += sB[k];
            g_Bpart[bg*NCHUNK + chunk] = sb;
        }
    }
}

// ---------------------------------------------------------------------------
// Pass 4: x11 = softmax(GAP(x1)); weff[k,i] = sum_e w3[k,i,e]*x11[e]; beff.
// w3 staged coalesced into padded smem (stride 33 kills bank conflicts).
// ---------------------------------------------------------------------------
__global__ void pass4(const float* __restrict__ w3,
                      const float* __restrict__ b3,
                      const float* __restrict__ gamma,
                      const float* __restrict__ beta)
{
    __shared__ float x11sm[Dd];
    __shared__ float sw3[9*Dd*33];     // padded rows: [row][e] at row*33+e
    int bg = blockIdx.x;
    int tid = threadIdx.x;             // 288 threads

    // coalesced stage of w3 (9216 floats)
    for (int n = tid; n < 9*Dd*Dd; n += 288) {
        int row = n >> 5, e = n & 31;
        sw3[row*33 + e] = w3[n];
    }

    if (tid < 32) {
        int e = tid;
        float A = 0.f, Bs = 0.f;
        for (int c = 0; c < NCHUNK; ++c) {
            A  += g_Apart[(bg*NCHUNK + c)*Dd + e];
            Bs += g_Bpart[bg*NCHUNK + c];
        }
        float v = gamma[e] * (A - Bs) * (1.f/NPIX) + beta[e];
        float mx = wmax(v);
        float p = expf(v - mx);
        float ps = wsum(p);
        float x11 = p/ps;
        x11sm[e] = x11;
        float be = wsum(x11 * b3[e]);
        if (e == 0) g_beff[bg] = be;
    }
    __syncthreads();
    {
        int k = tid >> 5, i = tid & 31;   // 288 = 9*32 exactly
        const float* row = &sw3[(k*Dd + i)*33];
        float acc = 0.f;
#pragma unroll
        for (int e = 0; e < Dd; ++e) acc += row[e] * x11sm[e];
        g_weff[(bg*9 + k)*Dd + i] = acc;
    }
}

// ---------------------------------------------------------------------------
// Pass 5: per pixel: w1 (projected 3x3 conv), recompute LN -> w2, gate, out.
// 4 independent sums reduced in ONE interleaved butterfly ladder.
// ---------------------------------------------------------------------------
__global__ void pass5(const float* __restrict__ x, float* __restrict__ out)
{
    int bg = blockIdx.x / Hh, h = blockIdx.x % Hh;
    int b = bg >> 3, gi = bg & 7;
    int lane = threadIdx.x & 31, warp = threadIdx.x >> 5;   // 8 warps
    const float* xb = x + ((size_t)b*Hh)*Ww*Cc + gi*Dd + lane;
    float* ob = out + ((size_t)b*Hh)*Ww*Cc + gi*Dd + lane;

    float xhv  = g_xh[(bg*Hh + h)*Dd + lane];
    float cv   = g_c[bg*Dd + lane];
    float csum = g_csum[bg], cb = g_cb[bg], beff = g_beff[bg];
    float wk[9];
#pragma unroll
    for (int k = 0; k < 9; ++k) wk[k] = g_weff[(bg*9 + k)*Dd + lane];

    for (int w = warp; w < Ww; w += 8) {
        float conv = 0.f, gxc = 0.f;
#pragma unroll
        for (int dy = -1; dy <= 1; ++dy) {
            int hh = h + dy;
            if (hh < 0 || hh >= Hh) continue;
            const float* rp = xb + (size_t)hh*Ww*Cc;
#pragma unroll
            for (int dx = -1; dx <= 1; ++dx) {
                int ww = w + dx;
                if (ww < 0 || ww >= Ww) continue;
                float v = rp[(size_t)ww*Cc];
                conv += v * wk[(dy+1)*3 + (dx+1)];
                if (dy == 0 && dx == 0) gxc = v;
            }
        }
        float y  = gxc * xhv * g_xw[(bg*Ww + w)*Dd + lane];
        float s0 = conv, s1 = y, s2 = y*y, s3 = cv*y;
#pragma unroll
        for (int o = 16; o; o >>= 1) {
            s0 += __shfl_xor_sync(0xffffffffu, s0, o);
            s1 += __shfl_xor_sync(0xffffffffu, s1, o);
            s2 += __shfl_xor_sync(0xffffffffu, s2, o);
            s3 += __shfl_xor_sync(0xffffffffu, s3, o);
        }
        float w1  = s0 + beff;
        float mu  = s1 * (1.f/Dd);
        float var = s2 * (1.f/Dd) - mu*mu;
        float rs  = rsqrtf(var + LN_EPS);
        float w2  = rs * (s3 - mu*csum) + cb;
        float gate = 1.f/(1.f + expf(-(w1 + w2)));
        ob[((size_t)h*Ww + w)*Cc] = gxc * gate;
    }
}

// ---------------------------------------------------------------------------
extern "C" void kernel_launch(void* const* d_in, const int* in_sizes, int n_in,
                              void* d_out, int out_size)
{
    const float* x   = (const float*)d_in[0];
    const float* w1  = (const float*)d_in[1];
    const float* b1  = (const float*)d_in[2];
    const float* w3  = (const float*)d_in[3];
    const float* b3  = (const float*)d_in[4];
    const float* gm  = (const float*)d_in[5];
    const float* bt  = (const float*)d_in[6];
    float* out = (float*)d_out;

    pass1<<<BG, 256>>>(x);
    pass2<<<BG, 128>>>(x, w1, b1, w3, b3, gm, bt);
    pass3<<<BG*NCHUNK, 512>>>(x);
    pass4<<<BG, 288>>>(w3, b3, gm, bt);
    pass5<<<BG*Hh, 256>>>(x, out);
}

// round 5
// speedup vs baseline: 1.2426x; 1.2332x over previous
#include <cuda_runtime.h>
#include <math.h>

// Problem shape (fixed by setup_inputs)
#define Bb   32
#define Hh   64
#define Ww   48
#define Cc   256
#define Dd   32
#define BG   256            // Bb * groups(8)
#define NPIX (Hh*Ww)        // 3072
#define LN_EPS 1e-3f

// Scratch (device globals — no allocation allowed)
__device__ float g_xh[BG*Hh*Dd];
__device__ float g_xw[BG*Ww*Dd];
__device__ float g_c[BG*Dd];       // x21 * gamma
__device__ float g_csum[BG];       // sum(x21*gamma)
__device__ float g_cb[BG];         // dot(x21, beta)
__device__ float g_A[BG*Dd];       // sum rs*y_e
__device__ float g_B[BG];          // sum rs*mu
__device__ float g_weff[BG*9*Dd];  // x11-projected conv3x3 kernel
__device__ float g_beff[BG];       // dot(x11, conv3x3_b)

__device__ __forceinline__ float wsum(float v){
#pragma unroll
    for (int o = 16; o; o >>= 1) v += __shfl_xor_sync(0xffffffffu, v, o);
    return v;
}
__device__ __forceinline__ float wmax(float v){
#pragma unroll
    for (int o = 16; o; o >>= 1) v = fmaxf(v, __shfl_xor_sync(0xffffffffu, v, o));
    return v;
}

// ---------------------------------------------------------------------------
// Fused pass 1+2+3: one block (512 thr, 16 warps) per bg.
//  A: single sweep of x -> row means (smem) + col sums (smem atomics)
//  B: warps 1..15: conv1x1 + sigmoid gates -> smem + gmem
//  C: warp 0 (concurrent with B): analytic mean(x2) -> x21 -> c, csum, cb
//  D: LN-stat sweep over own bg (L2-hot x, smem gates) -> g_A, g_B
// ---------------------------------------------------------------------------
__global__ void fused123(const float* __restrict__ x,
                         const float* __restrict__ w1x1,
                         const float* __restrict__ b1,
                         const float* __restrict__ w3,
                         const float* __restrict__ b3,
                         const float* __restrict__ gamma,
                         const float* __restrict__ beta)
{
    __shared__ float s_row[Hh][Dd];    // row means
    __shared__ float s_col[Ww][Dd];    // col SUMS (over 64 rows)
    __shared__ float s_xh[Hh][Dd];
    __shared__ float s_xw[Ww][Dd];
    __shared__ float smW[Dd*Dd];
    __shared__ float smS[9*Dd];
    __shared__ float sA[16*Dd];
    __shared__ float sB[16];

    int bg = blockIdx.x;
    int b = bg >> 3, gi = bg & 7;
    int tid = threadIdx.x, lane = tid & 31, warp = tid >> 5;   // 16 warps
    const float* xb = x + ((size_t)b*Hh)*Ww*Cc + gi*Dd + lane;

    // stage conv1x1 weights; zero col accumulators
    for (int i = tid; i < Dd*Dd; i += 512) smW[i] = w1x1[i];
    for (int i = tid; i < Ww*Dd; i += 512) (&s_col[0][0])[i] = 0.f;
    __syncthreads();

    // ---- Phase A: warp handles 4 rows ----
    {
        int r0 = warp * 4;
        float racc[4] = {0.f, 0.f, 0.f, 0.f};
#pragma unroll 2
        for (int w = 0; w < Ww; ++w) {
            float cacc = 0.f;
#pragma unroll
            for (int r = 0; r < 4; ++r) {
                float v = xb[((size_t)(r0 + r)*Ww + w)*Cc];
                racc[r] += v;
                cacc += v;
            }
            atomicAdd(&s_col[w][lane], cacc);
        }
#pragma unroll
        for (int r = 0; r < 4; ++r)
            s_row[r0 + r][lane] = racc[r] * (1.0f/Ww);
    }
    __syncthreads();

    // ---- Phase B (warps 1..15) / Phase C (warp 0), concurrent ----
    if (warp > 0) {
        float bias = b1[lane];
        for (int p = warp - 1; p < Hh + Ww; p += 15) {
            float v = (p < Hh) ? s_row[p][lane]
                               : s_col[p - Hh][lane] * (1.0f/Hh);
            float acc = bias;
#pragma unroll
            for (int i = 0; i < Dd; ++i) {
                float vi = __shfl_sync(0xffffffffu, v, i);
                acc += vi * smW[i*Dd + lane];
            }
            float s = 1.f/(1.f + expf(-acc));
            if (p < Hh) { s_xh[p][lane] = s;      g_xh[(bg*Hh + p)*Dd + lane] = s; }
            else        { s_xw[p-Hh][lane] = s;   g_xw[(bg*Ww + (p - Hh))*Dd + lane] = s; }
        }
    } else {
        int i = lane;
        float T = 0.f;
#pragma unroll 8
        for (int h = 0; h < Hh; ++h) T += s_row[h][i];
        T *= (float)Ww;
        float R0 = s_row[0     ][i] * (float)Ww;
        float RL = s_row[Hh - 1][i] * (float)Ww;
        float C0 = s_col[0     ][i];           // raw col sums == colmean*Hh
        float CL = s_col[Ww - 1][i];
        float ctl = xb[0];
        float ctr = xb[(size_t)(Ww-1)*Cc];
        float cbl = xb[((size_t)(Hh-1)*Ww)*Cc];
        float cbr = xb[((size_t)(Hh-1)*Ww + (Ww-1))*Cc];
#pragma unroll
        for (int dy = -1; dy <= 1; ++dy) {
#pragma unroll
            for (int dx = -1; dx <= 1; ++dx) {
                float eR = (dy == -1) ? RL : (dy == 1) ? R0 : 0.f;
                float eC = (dx == -1) ? CL : (dx == 1) ? C0 : 0.f;
                float corner = 0.f;
                if (dy == -1 && dx == -1) corner = cbr;
                if (dy == -1 && dx ==  1) corner = cbl;
                if (dy ==  1 && dx == -1) corner = ctr;
                if (dy ==  1 && dx ==  1) corner = ctl;
                smS[((dy+1)*3 + (dx+1))*Dd + i] = T - eR - eC + corner;
            }
        }
        __syncwarp();
        int e = lane;
        float acc = 0.f;
        for (int k = 0; k < 9; ++k) {
#pragma unroll
            for (int ii = 0; ii < Dd; ++ii)
                acc += w3[(k*Dd + ii)*Dd + e] * smS[k*Dd + ii];
        }
        float m2 = acc * (1.f/NPIX) + b3[e];
        float mx = wmax(m2);
        float pz = expf(m2 - mx);
        float ps = wsum(pz);
        float x21 = pz/ps;
        float cv = x21 * gamma[e];
        g_c[bg*Dd + e] = cv;
        float cs  = wsum(cv);
        float cbv = wsum(x21 * beta[e]);
        if (e == 0) { g_csum[bg] = cs; g_cb[bg] = cbv; }
    }
    __syncthreads();

    // ---- Phase D: LN-stat sweep, 4 pixels/iter, 8 interleaved butterflies ----
    {
        float accA = 0.f, accB = 0.f;
        int p0 = warp * 192;
        for (int j = 0; j < 192; j += 4) {
            int p = p0 + j;
            int h0 = (p+0) / Ww, w0 = (p+0) - h0*Ww;
            int h1 = (p+1) / Ww, w1 = (p+1) - h1*Ww;
            int h2 = (p+2) / Ww, w2 = (p+2) - h2*Ww;
            int h3 = (p+3) / Ww, w3i = (p+3) - h3*Ww;
            float gx0 = xb[(size_t)(p+0)*Cc];
            float gx1 = xb[(size_t)(p+1)*Cc];
            float gx2 = xb[(size_t)(p+2)*Cc];
            float gx3 = xb[(size_t)(p+3)*Cc];
            float y0 = gx0 * s_xh[h0][lane] * s_xw[w0][lane];
            float y1 = gx1 * s_xh[h1][lane] * s_xw[w1][lane];
            float y2 = gx2 * s_xh[h2][lane] * s_xw[w2][lane];
            float y3 = gx3 * s_xh[h3][lane] * s_xw[w3i][lane];
            float a0 = y0, b0 = y0*y0, a1 = y1, b1_ = y1*y1;
            float a2 = y2, b2 = y2*y2, a3 = y3, b3_ = y3*y3;
#pragma unroll
            for (int o = 16; o; o >>= 1) {
                a0 += __shfl_xor_sync(0xffffffffu, a0, o);
                b0 += __shfl_xor_sync(0xffffffffu, b0, o);
                a1 += __shfl_xor_sync(0xffffffffu, a1, o);
                b1_ += __shfl_xor_sync(0xffffffffu, b1_, o);
                a2 += __shfl_xor_sync(0xffffffffu, a2, o);
                b2 += __shfl_xor_sync(0xffffffffu, b2, o);
                a3 += __shfl_xor_sync(0xffffffffu, a3, o);
                b3_ += __shfl_xor_sync(0xffffffffu, b3_, o);
            }
            float mu0 = a0*(1.f/Dd), v0 = b0*(1.f/Dd) - mu0*mu0;
            float mu1 = a1*(1.f/Dd), v1 = b1_*(1.f/Dd) - mu1*mu1;
            float mu2 = a2*(1.f/Dd), v2 = b2*(1.f/Dd) - mu2*mu2;
            float mu3 = a3*(1.f/Dd), v3 = b3_*(1.f/Dd) - mu3*mu3;
            float r0_ = rsqrtf(v0 + LN_EPS);
            float r1_ = rsqrtf(v1 + LN_EPS);
            float r2_ = rsqrtf(v2 + LN_EPS);
            float r3_ = rsqrtf(v3 + LN_EPS);
            accA += r0_*y0 + r1_*y1 + r2_*y2 + r3_*y3;
            accB += r0_*mu0 + r1_*mu1 + r2_*mu2 + r3_*mu3;
        }
        sA[warp*Dd + lane] = accA;
        if (lane == 0) sB[warp] = accB;
    }
    __syncthreads();
    if (warp == 0) {
        float s = 0.f;
#pragma unroll
        for (int k = 0; k < 16; ++k) s += sA[k*Dd + lane];
        g_A[bg*Dd + lane] = s;
        if (lane == 0) {
            float sb = 0.f;
#pragma unroll
            for (int k = 0; k < 16; ++k) sb += sB[k];
            g_B[bg] = sb;
        }
    }
}

// ---------------------------------------------------------------------------
// Pass 4: x11 = softmax(GAP(x1)); weff[k,i] = sum_e w3[k,i,e]*x11[e]; beff.
// w3 staged coalesced into padded smem (stride 33 kills bank conflicts).
// ---------------------------------------------------------------------------
__global__ void pass4(const float* __restrict__ w3,
                      const float* __restrict__ b3,
                      const float* __restrict__ gamma,
                      const float* __restrict__ beta)
{
    __shared__ float x11sm[Dd];
    __shared__ float sw3[9*Dd*33];     // padded rows: [row][e] at row*33+e
    int bg = blockIdx.x;
    int tid = threadIdx.x;             // 288 threads

    // coalesced stage of w3 (9216 floats)
    for (int n = tid; n < 9*Dd*Dd; n += 288) {
        int row = n >> 5, e = n & 31;
        sw3[row*33 + e] = w3[n];
    }

    if (tid < 32) {
        int e = tid;
        float A  = g_A[bg*Dd + e];
        float Bs = g_B[bg];
        float v = gamma[e] * (A - Bs) * (1.f/NPIX) + beta[e];
        float mx = wmax(v);
        float p = expf(v - mx);
        float ps = wsum(p);
        float x11 = p/ps;
        x11sm[e] = x11;
        float be = wsum(x11 * b3[e]);
        if (e == 0) g_beff[bg] = be;
    }
    __syncthreads();
    {
        int k = tid >> 5, i = tid & 31;   // 288 = 9*32 exactly
        const float* row = &sw3[(k*Dd + i)*33];
        float acc = 0.f;
#pragma unroll
        for (int e = 0; e < Dd; ++e) acc += row[e] * x11sm[e];
        g_weff[(bg*9 + k)*Dd + i] = acc;
    }
}

// ---------------------------------------------------------------------------
// Pass 5: per pixel: w1 (projected 3x3 conv), recompute LN -> w2, gate, out.
// 2 pixels per iteration -> 8 independent sums in one interleaved ladder,
// 18 conv loads in flight.
// ---------------------------------------------------------------------------
__global__ void pass5(const float* __restrict__ x, float* __restrict__ out)
{
    int bg = blockIdx.x / Hh, h = blockIdx.x % Hh;
    int b = bg >> 3, gi = bg & 7;
    int lane = threadIdx.x & 31, warp = threadIdx.x >> 5;   // 8 warps
    const float* xb = x + ((size_t)b*Hh)*Ww*Cc + gi*Dd + lane;
    float* ob = out + ((size_t)b*Hh)*Ww*Cc + gi*Dd + lane;

    float xhv  = g_xh[(bg*Hh + h)*Dd + lane];
    float cv   = g_c[bg*Dd + lane];
    float csum = g_csum[bg], cb = g_cb[bg], beff = g_beff[bg];
    float wk[9];
#pragma unroll
    for (int k = 0; k < 9; ++k) wk[k] = g_weff[(bg*9 + k)*Dd + lane];

#pragma unroll
    for (int it = 0; it < 3; ++it) {
        int wA = warp + it*8;        // 0..23  (wA+dx >= -1, wA+dx <= 24 < Ww)
        int wB = wA + 24;            // 24..47 (wB+dx >= 23 >= 0, wB+dx <= 48)
        float convA = 0.f, convB = 0.f, gxA = 0.f, gxB = 0.f;
#pragma unroll
        for (int dy = -1; dy <= 1; ++dy) {
            int hh = h + dy;
            if (hh < 0 || hh >= Hh) continue;            // warp-uniform
            const float* rp = xb + (size_t)hh*Ww*Cc;
#pragma unroll
            for (int dx = -1; dx <= 1; ++dx) {
                int k = (dy+1)*3 + (dx+1);
                int wwA = wA + dx, wwB = wB + dx;
                if (wwA >= 0) {                          // warp-uniform
                    float v = rp[(size_t)wwA*Cc];
                    convA += v * wk[k];
                    if (dy == 0 && dx == 0) gxA = v;
                }
                if (wwB < Ww) {                          // warp-uniform
                    float v = rp[(size_t)wwB*Cc];
                    convB += v * wk[k];
                    if (dy == 0 && dx == 0) gxB = v;
                }
            }
        }
        float xwA = g_xw[(bg*Ww + wA)*Dd + lane];
        float xwB = g_xw[(bg*Ww + wB)*Dd + lane];
        float yA = gxA * xhv * xwA;
        float yB = gxB * xhv * xwB;
        float s0 = convA, s1 = yA, s2 = yA*yA, s3 = cv*yA;
        float s4 = convB, s5 = yB, s6 = yB*yB, s7 = cv*yB;
#pragma unroll
        for (int o = 16; o; o >>= 1) {
            s0 += __shfl_xor_sync(0xffffffffu, s0, o);
            s1 += __shfl_xor_sync(0xffffffffu, s1, o);
            s2 += __shfl_xor_sync(0xffffffffu, s2, o);
            s3 += __shfl_xor_sync(0xffffffffu, s3, o);
            s4 += __shfl_xor_sync(0xffffffffu, s4, o);
            s5 += __shfl_xor_sync(0xffffffffu, s5, o);
            s6 += __shfl_xor_sync(0xffffffffu, s6, o);
            s7 += __shfl_xor_sync(0xffffffffu, s7, o);
        }
        float w1A  = s0 + beff;
        float muA  = s1 * (1.f/Dd);
        float varA = s2 * (1.f/Dd) - muA*muA;
        float rsA  = rsqrtf(varA + LN_EPS);
        float w2A  = rsA * (s3 - muA*csum) + cb;
        float gateA = 1.f/(1.f + expf(-(w1A + w2A)));

        float w1B  = s4 + beff;
        float muB  = s5 * (1.f/Dd);
        float varB = s6 * (1.f/Dd) - muB*muB;
        float rsB  = rsqrtf(varB + LN_EPS);
        float w2B  = rsB * (s7 - muB*csum) + cb;
        float gateB = 1.f/(1.f + expf(-(w1B + w2B)));

        ob[((size_t)h*Ww + wA)*Cc] = gxA * gateA;
        ob[((size_t)h*Ww + wB)*Cc] = gxB * gateB;
    }
}

// ---------------------------------------------------------------------------
extern "C" void kernel_launch(void* const* d_in, const int* in_sizes, int n_in,
                              void* d_out, int out_size)
{
    const float* x   = (const float*)d_in[0];
    const float* w1  = (const float*)d_in[1];
    const float* b1  = (const float*)d_in[2];
    const float* w3  = (const float*)d_in[3];
    const float* b3  = (const float*)d_in[4];
    const float* gm  = (const float*)d_in[5];
    const float* bt  = (const float*)d_in[6];
    float* out = (float*)d_out;

    fused123<<<BG, 512>>>(x, w1, b1, w3, b3, gm, bt);
    pass4<<<BG, 288>>>(w3, b3, gm, bt);
    pass5<<<BG*Hh, 256>>>(x, out);
}

// round 6
// speedup vs baseline: 1.4683x; 1.1816x over previous
#include <cuda_runtime.h>
#include <math.h>

// Problem shape (fixed by setup_inputs)
#define Bb   32
#define Hh   64
#define Ww   48
#define Cc   256
#define Dd   32
#define BG   256            // Bb * groups(8)
#define NPIX (Hh*Ww)        // 3072
#define LN_EPS 1e-3f

// Scratch (device globals — no allocation allowed)
__device__ float g_xh[BG*Hh*Dd];
__device__ float g_xw[BG*Ww*Dd];
__device__ float g_c[BG*Dd];       // x21 * gamma
__device__ float g_csum[BG];       // sum(x21*gamma)
__device__ float g_cb[BG];         // dot(x21, beta)
__device__ float g_A[BG*Dd];       // sum rs*y_e
__device__ float g_B[BG];          // sum rs*mu
__device__ float g_weff[BG*9*Dd];  // x11-projected conv3x3 kernel
__device__ float g_beff[BG];       // dot(x11, conv3x3_b)

__device__ __forceinline__ float wsum(float v){
#pragma unroll
    for (int o = 16; o; o >>= 1) v += __shfl_xor_sync(0xffffffffu, v, o);
    return v;
}
__device__ __forceinline__ float wmax(float v){
#pragma unroll
    for (int o = 16; o; o >>= 1) v = fmaxf(v, __shfl_xor_sync(0xffffffffu, v, o));
    return v;
}

// ---------------------------------------------------------------------------
// Fused pass 1+2+3: one block (512 thr, 16 warps) per bg. Quad/float4 layout:
// lane = sg*8 + cg, sg = lane>>3 (pixel/row subgroup), ch0 = (lane&7)*4.
// ---------------------------------------------------------------------------
__global__ void fused123(const float* __restrict__ x,
                         const float* __restrict__ w1x1,
                         const float* __restrict__ b1,
                         const float* __restrict__ w3,
                         const float* __restrict__ b3,
                         const float* __restrict__ gamma,
                         const float* __restrict__ beta)
{
    __shared__ __align__(16) float s_row[Hh][Dd];    // row means
    __shared__ __align__(16) float s_col[Ww][Dd];    // col SUMS (over 64 rows)
    __shared__ __align__(16) float s_xh[Hh][Dd];
    __shared__ __align__(16) float s_xw[Ww][Dd];
    __shared__ float smW[Dd*Dd];
    __shared__ float smS[9*Dd];
    __shared__ __align__(16) float sA[16][Dd];
    __shared__ float sB[16];

    int bg = blockIdx.x;
    int b = bg >> 3, gi = bg & 7;
    int tid = threadIdx.x, lane = tid & 31, warp = tid >> 5;   // 16 warps
    int sg = lane >> 3, ch0 = (lane & 7) * 4;
    const float* xg = x + ((size_t)b*Hh)*Ww*Cc + gi*Dd + ch0;  // float4 base
    const float* xb = x + ((size_t)b*Hh)*Ww*Cc + gi*Dd + lane; // scalar base

    for (int i = tid; i < Dd*Dd; i += 512) smW[i] = w1x1[i];
    for (int i = tid; i < Ww*Dd; i += 512) (&s_col[0][0])[i] = 0.f;
    __syncthreads();

    // ---- Phase A: warp handles 4 rows (row r = warp*4 + sg per subgroup) ----
    {
        int r = warp * 4 + sg;
        const float* rp = xg + (size_t)r*Ww*Cc;
        float4 racc = make_float4(0.f,0.f,0.f,0.f);
        for (int w = 0; w < Ww; ++w) {
            float4 v = *(const float4*)(rp + (size_t)w*Cc);
            racc.x += v.x; racc.y += v.y; racc.z += v.z; racc.w += v.w;
            // combine over the 4 rows (subgroups) for col sums
            float cx = v.x, cy = v.y, cz = v.z, cw = v.w;
#pragma unroll
            for (int o = 8; o <= 16; o <<= 1) {
                cx += __shfl_xor_sync(0xffffffffu, cx, o);
                cy += __shfl_xor_sync(0xffffffffu, cy, o);
                cz += __shfl_xor_sync(0xffffffffu, cz, o);
                cw += __shfl_xor_sync(0xffffffffu, cw, o);
            }
            if (sg == 0) {
                atomicAdd(&s_col[w][ch0+0], cx);
                atomicAdd(&s_col[w][ch0+1], cy);
                atomicAdd(&s_col[w][ch0+2], cz);
                atomicAdd(&s_col[w][ch0+3], cw);
            }
        }
        racc.x *= (1.0f/Ww); racc.y *= (1.0f/Ww); racc.z *= (1.0f/Ww); racc.w *= (1.0f/Ww);
        *(float4*)&s_row[r][ch0] = racc;
    }
    __syncthreads();

    // ---- Phase B (warps 1..15) / Phase C (warp 0), concurrent ----
    if (warp > 0) {
        float bias = b1[lane];
        for (int p = warp - 1; p < Hh + Ww; p += 15) {
            float v = (p < Hh) ? s_row[p][lane]
                               : s_col[p - Hh][lane] * (1.0f/Hh);
            float acc = bias;
#pragma unroll
            for (int i = 0; i < Dd; ++i) {
                float vi = __shfl_sync(0xffffffffu, v, i);
                acc += vi * smW[i*Dd + lane];
            }
            float s = 1.f/(1.f + expf(-acc));
            if (p < Hh) { s_xh[p][lane] = s;      g_xh[(bg*Hh + p)*Dd + lane] = s; }
            else        { s_xw[p-Hh][lane] = s;   g_xw[(bg*Ww + (p - Hh))*Dd + lane] = s; }
        }
    } else {
        int i = lane;
        float T = 0.f;
#pragma unroll 8
        for (int h = 0; h < Hh; ++h) T += s_row[h][i];
        T *= (float)Ww;
        float R0 = s_row[0     ][i] * (float)Ww;
        float RL = s_row[Hh - 1][i] * (float)Ww;
        float C0 = s_col[0     ][i];           // raw col sums == colmean*Hh
        float CL = s_col[Ww - 1][i];
        float ctl = xb[0];
        float ctr = xb[(size_t)(Ww-1)*Cc];
        float cbl = xb[((size_t)(Hh-1)*Ww)*Cc];
        float cbr = xb[((size_t)(Hh-1)*Ww + (Ww-1))*Cc];
#pragma unroll
        for (int dy = -1; dy <= 1; ++dy) {
#pragma unroll
            for (int dx = -1; dx <= 1; ++dx) {
                float eR = (dy == -1) ? RL : (dy == 1) ? R0 : 0.f;
                float eC = (dx == -1) ? CL : (dx == 1) ? C0 : 0.f;
                float corner = 0.f;
                if (dy == -1 && dx == -1) corner = cbr;
                if (dy == -1 && dx ==  1) corner = cbl;
                if (dy ==  1 && dx == -1) corner = ctr;
                if (dy ==  1 && dx ==  1) corner = ctl;
                smS[((dy+1)*3 + (dx+1))*Dd + i] = T - eR - eC + corner;
            }
        }
        __syncwarp();
        int e = lane;
        float acc = 0.f;
        for (int k = 0; k < 9; ++k) {
#pragma unroll
            for (int ii = 0; ii < Dd; ++ii)
                acc += w3[(k*Dd + ii)*Dd + e] * smS[k*Dd + ii];
        }
        float m2 = acc * (1.f/NPIX) + b3[e];
        float mx = wmax(m2);
        float pz = expf(m2 - mx);
        float ps = wsum(pz);
        float x21 = pz/ps;
        float cv = x21 * gamma[e];
        g_c[bg*Dd + e] = cv;
        float cs  = wsum(cv);
        float cbv = wsum(x21 * beta[e]);
        if (e == 0) { g_csum[bg] = cs; g_cb[bg] = cbv; }
    }
    __syncthreads();

    // ---- Phase D: LN-stat sweep, 4 pixels per warp-step (quad layout) ----
    {
        float4 accA = make_float4(0.f,0.f,0.f,0.f);
        float accB = 0.f;
        int p0 = warp * 192;
#pragma unroll 2
        for (int j = 0; j < 192; j += 4) {
            int p = p0 + j + sg;
            int h = p / Ww, w = p - h*Ww;
            float4 gx = *(const float4*)(xg + (size_t)p*Cc);
            float4 xh = *(const float4*)&s_xh[h][ch0];
            float4 xw = *(const float4*)&s_xw[w][ch0];
            float4 y;
            y.x = gx.x*xh.x*xw.x; y.y = gx.y*xh.y*xw.y;
            y.z = gx.z*xh.z*xw.z; y.w = gx.w*xh.w*xw.w;
            float a = (y.x + y.y) + (y.z + y.w);
            float bq = (y.x*y.x + y.y*y.y) + (y.z*y.z + y.w*y.w);
#pragma unroll
            for (int o = 4; o; o >>= 1) {
                a  += __shfl_xor_sync(0xffffffffu, a,  o);
                bq += __shfl_xor_sync(0xffffffffu, bq, o);
            }
            float mu = a * (1.f/Dd);
            float var = bq * (1.f/Dd) - mu*mu;
            float rs = rsqrtf(var + LN_EPS);
            accA.x += rs*y.x; accA.y += rs*y.y; accA.z += rs*y.z; accA.w += rs*y.w;
            accB += rs*mu;
        }
        // combine channel sums across the 4 subgroups
#pragma unroll
        for (int o = 8; o <= 16; o <<= 1) {
            accA.x += __shfl_xor_sync(0xffffffffu, accA.x, o);
            accA.y += __shfl_xor_sync(0xffffffffu, accA.y, o);
            accA.z += __shfl_xor_sync(0xffffffffu, accA.z, o);
            accA.w += __shfl_xor_sync(0xffffffffu, accA.w, o);
        }
        if (sg == 0) *(float4*)&sA[warp][ch0] = accA;
        float bt = wsum(accB) * 0.125f;   // each pixel counted by 8 lanes
        if (lane == 0) sB[warp] = bt;
    }
    __syncthreads();
    if (warp == 0) {
        float s = 0.f;
#pragma unroll
        for (int k = 0; k < 16; ++k) s += sA[k][lane];
        g_A[bg*Dd + lane] = s;
        if (lane == 0) {
            float sb = 0.f;
#pragma unroll
            for (int k = 0; k < 16; ++k) sb += sB[k];
            g_B[bg] = sb;
        }
    }
}

// ---------------------------------------------------------------------------
// Pass 4: x11 = softmax(GAP(x1)); weff[k,i] = sum_e w3[k,i,e]*x11[e]; beff.
// 2 bg per block: w3 staged once (padded smem, stride 33), used twice.
// ---------------------------------------------------------------------------
__global__ void pass4(const float* __restrict__ w3,
                      const float* __restrict__ b3,
                      const float* __restrict__ gamma,
                      const float* __restrict__ beta)
{
    __shared__ float x11sm[2][Dd];
    __shared__ float sw3[9*Dd*33];     // padded rows: [row][e] at row*33+e
    int bg0 = blockIdx.x * 2;
    int tid = threadIdx.x;             // 288 threads

    for (int n = tid; n < 9*Dd*Dd; n += 288) {
        int row = n >> 5, e = n & 31;
        sw3[row*33 + e] = w3[n];
    }

    if (tid < 64) {
        int bgl = tid >> 5, e = tid & 31;
        int bg = bg0 + bgl;
        float A  = g_A[bg*Dd + e];
        float Bs = g_B[bg];
        float v = gamma[e] * (A - Bs) * (1.f/NPIX) + beta[e];
        float mx = v;
#pragma unroll
        for (int o = 16; o; o >>= 1) mx = fmaxf(mx, __shfl_xor_sync(0xffffffffu, mx, o));
        float p = expf(v - mx);
        float ps = p;
#pragma unroll
        for (int o = 16; o; o >>= 1) ps += __shfl_xor_sync(0xffffffffu, ps, o);
        float x11 = p/ps;
        x11sm[bgl][e] = x11;
        float be = x11 * b3[e];
#pragma unroll
        for (int o = 16; o; o >>= 1) be += __shfl_xor_sync(0xffffffffu, be, o);
        if (e == 0) g_beff[bg] = be;
    }
    __syncthreads();
    {
        int k = tid >> 5, i = tid & 31;   // 288 = 9*32 exactly
        const float* row = &sw3[(k*Dd + i)*33];
#pragma unroll
        for (int bgl = 0; bgl < 2; ++bgl) {
            float acc = 0.f;
#pragma unroll
            for (int e = 0; e < Dd; ++e) acc += row[e] * x11sm[bgl][e];
            g_weff[((bg0 + bgl)*9 + k)*Dd + i] = acc;
        }
    }
}

// ---------------------------------------------------------------------------
// Pass 5: per pixel: w1 (projected 3x3 conv), recompute LN -> w2, gate, out.
// Quad layout: warp = 4 pixels, lane covers 4 channels (float4).
// One block per (bg, row-pair): 96 pixels, 8 warps, 3 quad-iterations.
// ---------------------------------------------------------------------------
__global__ void pass5(const float* __restrict__ x, float* __restrict__ out)
{
    int bg = blockIdx.x >> 5;
    int h0 = (blockIdx.x & 31) * 2;
    int b = bg >> 3, gi = bg & 7;
    int lane = threadIdx.x & 31, warp = threadIdx.x >> 5;   // 8 warps
    int sg = lane >> 3, ch0 = (lane & 7) * 4;
    const float* xg = x + ((size_t)b*Hh)*Ww*Cc + gi*Dd + ch0;
    float* og = out + ((size_t)b*Hh)*Ww*Cc + gi*Dd + ch0;

    float4 cv   = *(const float4*)&g_c[bg*Dd + ch0];
    float csum = g_csum[bg], cb = g_cb[bg], beff = g_beff[bg];
    float4 wk[9];
#pragma unroll
    for (int k = 0; k < 9; ++k) wk[k] = *(const float4*)&g_weff[(bg*9 + k)*Dd + ch0];

#pragma unroll
    for (int it = 0; it < 3; ++it) {
        int q = it*32 + warp*4 + sg;          // 0..95
        int h = h0 + (q >= Ww ? 1 : 0);
        int w = q - (q >= Ww ? Ww : 0);

        float cx = 0.f, cy = 0.f, cz = 0.f, cw = 0.f;
        float4 gx;
#pragma unroll
        for (int dy = -1; dy <= 1; ++dy) {
            int hh = h + dy;
            bool okh = ((unsigned)hh < (unsigned)Hh);
#pragma unroll
            for (int dx = -1; dx <= 1; ++dx) {
                int ww = w + dx;
                bool ok = okh && ((unsigned)ww < (unsigned)Ww);
                float4 v = make_float4(0.f,0.f,0.f,0.f);
                if (ok) v = *(const float4*)(xg + ((size_t)hh*Ww + ww)*Cc);
                int k = (dy+1)*3 + (dx+1);
                cx = fmaf(v.x, wk[k].x, cx);
                cy = fmaf(v.y, wk[k].y, cy);
                cz = fmaf(v.z, wk[k].z, cz);
                cw = fmaf(v.w, wk[k].w, cw);
                if (dy == 0 && dx == 0) gx = v;
            }
        }
        float conv = (cx + cy) + (cz + cw);

        float4 xh = *(const float4*)&g_xh[(bg*Hh + h)*Dd + ch0];
        float4 xw = *(const float4*)&g_xw[(bg*Ww + w)*Dd + ch0];
        float4 y;
        y.x = gx.x*xh.x*xw.x; y.y = gx.y*xh.y*xw.y;
        y.z = gx.z*xh.z*xw.z; y.w = gx.w*xh.w*xw.w;
        float s1 = (y.x + y.y) + (y.z + y.w);
        float s2 = (y.x*y.x + y.y*y.y) + (y.z*y.z + y.w*y.w);
        float s3 = (cv.x*y.x + cv.y*y.y) + (cv.z*y.z + cv.w*y.w);
#pragma unroll
        for (int o = 4; o; o >>= 1) {
            conv += __shfl_xor_sync(0xffffffffu, conv, o);
            s1   += __shfl_xor_sync(0xffffffffu, s1,   o);
            s2   += __shfl_xor_sync(0xffffffffu, s2,   o);
            s3   += __shfl_xor_sync(0xffffffffu, s3,   o);
        }
        float w1  = conv + beff;
        float mu  = s1 * (1.f/Dd);
        float var = s2 * (1.f/Dd) - mu*mu;
        float rs  = rsqrtf(var + LN_EPS);
        float w2  = rs * (s3 - mu*csum) + cb;
        float gate = 1.f/(1.f + expf(-(w1 + w2)));

        float4 o4;
        o4.x = gx.x*gate; o4.y = gx.y*gate; o4.z = gx.z*gate; o4.w = gx.w*gate;
        *(float4*)(og + ((size_t)h*Ww + w)*Cc) = o4;
    }
}

// ---------------------------------------------------------------------------
extern "C" void kernel_launch(void* const* d_in, const int* in_sizes, int n_in,
                              void* d_out, int out_size)
{
    const float* x   = (const float*)d_in[0];
    const float* w1  = (const float*)d_in[1];
    const float* b1  = (const float*)d_in[2];
    const float* w3  = (const float*)d_in[3];
    const float* b3  = (const float*)d_in[4];
    const float* gm  = (const float*)d_in[5];
    const float* bt  = (const float*)d_in[6];
    float* out = (float*)d_out;

    fused123<<<BG, 512>>>(x, w1, b1, w3, b3, gm, bt);
    pass4<<<BG/2, 288>>>(w3, b3, gm, bt);
    pass5<<<BG*(Hh/2), 256>>>(x, out);
}

// round 7
// speedup vs baseline: 1.7658x; 1.2026x over previous
#include <cuda_runtime.h>
#include <math.h>

// Problem shape (fixed by setup_inputs)
#define Bb   32
#define Hh   64
#define Ww   48
#define Cc   256
#define Dd   32
#define BG   256            // Bb * groups(8)
#define NPIX (Hh*Ww)        // 3072
#define LN_EPS 1e-3f

// Scratch (device globals — no allocation allowed)
__device__ float g_xh[BG*Hh*Dd];
__device__ float g_xw[BG*Ww*Dd];
__device__ float g_c[BG*Dd];       // x21 * gamma
__device__ float g_csum[BG];       // sum(x21*gamma)
__device__ float g_cb[BG];         // dot(x21, beta)
__device__ float g_weff[BG*9*Dd];  // x11-projected conv3x3 kernel
__device__ float g_beff[BG];       // dot(x11, conv3x3_b)

__device__ __forceinline__ float wsum(float v){
#pragma unroll
    for (int o = 16; o; o >>= 1) v += __shfl_xor_sync(0xffffffffu, v, o);
    return v;
}
__device__ __forceinline__ float wmax(float v){
#pragma unroll
    for (int o = 16; o; o >>= 1) v = fmaxf(v, __shfl_xor_sync(0xffffffffu, v, o));
    return v;
}

// Dynamic smem layout for fused kernel (floats):
#define F_ROW   0                  // s_row[64][32]
#define F_COLP  2048               // s_colp[4][48][32]
#define F_XH    8192               // s_xh[64][32]
#define F_XW    10240              // s_xw[48][32]
#define F_W1    11776              // smW[1024]
#define F_S9    12800              // smS[288]
#define F_SA    13088              // sA[16][32]
#define F_SB    13600              // sB[16]
#define F_X11   13616              // x11[32]
#define F_TOTAL 13648              // floats -> 54592 bytes

// ---------------------------------------------------------------------------
// Fused pass 1+2+3+4: one block (512 thr, 16 warps) per bg.
// ---------------------------------------------------------------------------
__global__ void __launch_bounds__(512, 1)
fused1234(const float* __restrict__ x,
          const float* __restrict__ w1x1,
          const float* __restrict__ b1,
          const float* __restrict__ w3,
          const float* __restrict__ b3,
          const float* __restrict__ gamma,
          const float* __restrict__ beta)
{
    extern __shared__ float sm[];
    float (*s_row)[Dd]       = (float(*)[Dd])(sm + F_ROW);
    float (*s_colp)[Ww][Dd]  = (float(*)[Ww][Dd])(sm + F_COLP);
    float (*s_xh)[Dd]        = (float(*)[Dd])(sm + F_XH);
    float (*s_xw)[Dd]        = (float(*)[Dd])(sm + F_XW);
    float *smW = sm + F_W1;
    float *smS = sm + F_S9;
    float (*sA)[Dd]          = (float(*)[Dd])(sm + F_SA);
    float *sB  = sm + F_SB;
    float *x11 = sm + F_X11;

    int bg = blockIdx.x;
    int b = bg >> 3, gi = bg & 7;
    int tid = threadIdx.x, lane = tid & 31, warp = tid >> 5;   // 16 warps
    int sg = lane >> 3, ch0 = (lane & 7) * 4;
    const float* xg = x + ((size_t)b*Hh)*Ww*Cc + gi*Dd + ch0;  // float4 base
    const float* xb = x + ((size_t)b*Hh)*Ww*Cc + gi*Dd + lane; // scalar base

    // stage conv1x1 weights (sync provided by the col-reduce rounds below)
    for (int i = tid; i < Dd*Dd; i += 512) smW[i] = w1x1[i];

    // ---- Phase A: warp owns rows warp*4..+3; register col partials ----
    float4 cacc[12];
#pragma unroll
    for (int s = 0; s < 12; ++s) cacc[s] = make_float4(0.f,0.f,0.f,0.f);
    {
        int r0 = warp * 4;
#pragma unroll
        for (int r = 0; r < 4; ++r) {
            int row = r0 + r;
            const float* rp = xg + (size_t)row*Ww*Cc;
            float4 racc = make_float4(0.f,0.f,0.f,0.f);
#pragma unroll
            for (int s = 0; s < 12; ++s) {
                float4 v = *(const float4*)(rp + (size_t)(s*4 + sg)*Cc);
                cacc[s].x += v.x; cacc[s].y += v.y; cacc[s].z += v.z; cacc[s].w += v.w;
                racc.x += v.x; racc.y += v.y; racc.z += v.z; racc.w += v.w;
            }
#pragma unroll
            for (int o = 8; o <= 16; o <<= 1) {
                racc.x += __shfl_xor_sync(0xffffffffu, racc.x, o);
                racc.y += __shfl_xor_sync(0xffffffffu, racc.y, o);
                racc.z += __shfl_xor_sync(0xffffffffu, racc.z, o);
                racc.w += __shfl_xor_sync(0xffffffffu, racc.w, o);
            }
            if (sg == 0) {
                racc.x *= (1.f/Ww); racc.y *= (1.f/Ww); racc.z *= (1.f/Ww); racc.w *= (1.f/Ww);
                *(float4*)&s_row[row][ch0] = racc;
            }
        }
    }
    // staged (atomic-free) cross-warp col reduction into 4 slots
    {
        int slot = warp & 3, grp = warp >> 2;
        if (grp == 0) {
#pragma unroll
            for (int s = 0; s < 12; ++s)
                *(float4*)&s_colp[slot][s*4 + sg][ch0] = cacc[s];
        }
        __syncthreads();
#pragma unroll
        for (int rd = 1; rd < 4; ++rd) {
            if (grp == rd) {
#pragma unroll
                for (int s = 0; s < 12; ++s) {
                    float4 t = *(float4*)&s_colp[slot][s*4 + sg][ch0];
                    t.x += cacc[s].x; t.y += cacc[s].y; t.z += cacc[s].z; t.w += cacc[s].w;
                    *(float4*)&s_colp[slot][s*4 + sg][ch0] = t;
                }
            }
            __syncthreads();
        }
    }
    // now col SUM (over 64 rows) of [w][ch] = sum over 4 slots

    // ---- Phase B (warps 1..15) / Phase C (warp 0), concurrent ----
    if (warp > 0) {
        float bias = b1[lane];
        for (int p = warp - 1; p < Hh + Ww; p += 15) {
            float v;
            if (p < Hh) v = s_row[p][lane];
            else {
                int w = p - Hh;
                v = (s_colp[0][w][lane] + s_colp[1][w][lane]
                   + s_colp[2][w][lane] + s_colp[3][w][lane]) * (1.0f/Hh);
            }
            float acc = bias;
#pragma unroll
            for (int i = 0; i < Dd; ++i) {
                float vi = __shfl_sync(0xffffffffu, v, i);
                acc += vi * smW[i*Dd + lane];
            }
            float s = 1.f/(1.f + expf(-acc));
            if (p < Hh) { s_xh[p][lane] = s;      g_xh[(bg*Hh + p)*Dd + lane] = s; }
            else        { s_xw[p-Hh][lane] = s;   g_xw[(bg*Ww + (p - Hh))*Dd + lane] = s; }
        }
    } else {
        int i = lane;
        float T = 0.f;
#pragma unroll 8
        for (int h = 0; h < Hh; ++h) T += s_row[h][i];
        T *= (float)Ww;
        float R0 = s_row[0     ][i] * (float)Ww;
        float RL = s_row[Hh - 1][i] * (float)Ww;
        float C0 = s_colp[0][0][i] + s_colp[1][0][i] + s_colp[2][0][i] + s_colp[3][0][i];
        float CL = s_colp[0][Ww-1][i] + s_colp[1][Ww-1][i] + s_colp[2][Ww-1][i] + s_colp[3][Ww-1][i];
        float ctl = xb[0];
        float ctr = xb[(size_t)(Ww-1)*Cc];
        float cbl = xb[((size_t)(Hh-1)*Ww)*Cc];
        float cbr = xb[((size_t)(Hh-1)*Ww + (Ww-1))*Cc];
#pragma unroll
        for (int dy = -1; dy <= 1; ++dy) {
#pragma unroll
            for (int dx = -1; dx <= 1; ++dx) {
                float eR = (dy == -1) ? RL : (dy == 1) ? R0 : 0.f;
                float eC = (dx == -1) ? CL : (dx == 1) ? C0 : 0.f;
                float corner = 0.f;
                if (dy == -1 && dx == -1) corner = cbr;
                if (dy == -1 && dx ==  1) corner = cbl;
                if (dy ==  1 && dx == -1) corner = ctr;
                if (dy ==  1 && dx ==  1) corner = ctl;
                smS[((dy+1)*3 + (dx+1))*Dd + i] = T - eR - eC + corner;
            }
        }
        __syncwarp();
        int e = lane;
        float acc = 0.f;
        for (int k = 0; k < 9; ++k) {
#pragma unroll
            for (int ii = 0; ii < Dd; ++ii)
                acc += w3[(k*Dd + ii)*Dd + e] * smS[k*Dd + ii];
        }
        float m2 = acc * (1.f/NPIX) + b3[e];
        float mx = wmax(m2);
        float pz = expf(m2 - mx);
        float ps = wsum(pz);
        float x21 = pz/ps;
        float cv = x21 * gamma[e];
        g_c[bg*Dd + e] = cv;
        float cs  = wsum(cv);
        float cbv = wsum(x21 * beta[e]);
        if (e == 0) { g_csum[bg] = cs; g_cb[bg] = cbv; }
    }
    __syncthreads();

    // ---- Phase D: LN-stat sweep, 4 pixels per warp-step (quad layout) ----
    {
        float4 accA = make_float4(0.f,0.f,0.f,0.f);
        float accB = 0.f;
        int p0 = warp * 192;
#pragma unroll 2
        for (int j = 0; j < 192; j += 4) {
            int p = p0 + j + sg;
            int h = p / Ww, w = p - h*Ww;
            float4 gx = *(const float4*)(xg + (size_t)p*Cc);
            float4 xh = *(const float4*)&s_xh[h][ch0];
            float4 xw = *(const float4*)&s_xw[w][ch0];
            float4 y;
            y.x = gx.x*xh.x*xw.x; y.y = gx.y*xh.y*xw.y;
            y.z = gx.z*xh.z*xw.z; y.w = gx.w*xh.w*xw.w;
            float a = (y.x + y.y) + (y.z + y.w);
            float bq = (y.x*y.x + y.y*y.y) + (y.z*y.z + y.w*y.w);
#pragma unroll
            for (int o = 4; o; o >>= 1) {
                a  += __shfl_xor_sync(0xffffffffu, a,  o);
                bq += __shfl_xor_sync(0xffffffffu, bq, o);
            }
            float mu = a * (1.f/Dd);
            float var = bq * (1.f/Dd) - mu*mu;
            float rs = rsqrtf(var + LN_EPS);
            accA.x += rs*y.x; accA.y += rs*y.y; accA.z += rs*y.z; accA.w += rs*y.w;
            accB += rs*mu;
        }
#pragma unroll
        for (int o = 8; o <= 16; o <<= 1) {
            accA.x += __shfl_xor_sync(0xffffffffu, accA.x, o);
            accA.y += __shfl_xor_sync(0xffffffffu, accA.y, o);
            accA.z += __shfl_xor_sync(0xffffffffu, accA.z, o);
            accA.w += __shfl_xor_sync(0xffffffffu, accA.w, o);
        }
        if (sg == 0) *(float4*)&sA[warp][ch0] = accA;
        float bt = wsum(accB) * 0.125f;   // each pixel counted by 8 lanes
        if (lane == 0) sB[warp] = bt;
    }
    __syncthreads();

    // ---- Phase E: x11 softmax + beff (warp 0), then weff (288 threads) ----
    if (warp == 0) {
        int e = lane;
        float A = 0.f, Bs = 0.f;
#pragma unroll
        for (int k = 0; k < 16; ++k) { A += sA[k][e]; Bs += sB[k]; }
        float v = gamma[e] * (A - Bs) * (1.f/NPIX) + beta[e];
        float mx = wmax(v);
        float p = expf(v - mx);
        float ps = wsum(p);
        float xv = p/ps;
        x11[e] = xv;
        float be = wsum(xv * b3[e]);
        if (e == 0) g_beff[bg] = be;
    }
    __syncthreads();
    if (tid < 288) {
        int k = tid >> 5, i = tid & 31;
        const float4* wrow = (const float4*)(w3 + (size_t)(k*Dd + i)*Dd);
        float acc = 0.f;
#pragma unroll
        for (int e4 = 0; e4 < 8; ++e4) {
            float4 wv = __ldg(&wrow[e4]);
            acc += wv.x*x11[e4*4+0] + wv.y*x11[e4*4+1]
                 + wv.z*x11[e4*4+2] + wv.w*x11[e4*4+3];
        }
        g_weff[(bg*9 + k)*Dd + i] = acc;
    }
}

// Dynamic smem layout for pass5 (floats):
#define P_TILE  0                   // s_t[10][50][32]
#define P_GH    16000               // s_gh[8][32]
#define P_GW    16256               // s_gw[48][32]
#define P_WK    17792               // s_wk[9][32]
#define P_TOTAL 18080               // floats -> 72320 bytes

// ---------------------------------------------------------------------------
// Pass 5: smem-tiled. Block = (bg, 8-row band). 512 thr, 16 warps.
// Stage x[h0-1..h0+8][0..47] tile (+w halo) once; conv from LDS.
// ---------------------------------------------------------------------------
__global__ void __launch_bounds__(512, 2)
pass5(const float* __restrict__ x, float* __restrict__ out)
{
    extern __shared__ float sm[];
    float (*s_t)[50][Dd] = (float(*)[50][Dd])(sm + P_TILE);
    float (*s_gh)[Dd]    = (float(*)[Dd])(sm + P_GH);
    float (*s_gw)[Dd]    = (float(*)[Dd])(sm + P_GW);
    float (*s_wk)[Dd]    = (float(*)[Dd])(sm + P_WK);

    int bg = blockIdx.x >> 3;
    int h0 = (blockIdx.x & 7) * 8;
    int b = bg >> 3, gi = bg & 7;
    int tid = threadIdx.x, lane = tid & 31, warp = tid >> 5;   // 16 warps
    int sg = lane >> 3, ch0 = (lane & 7) * 4;
    const float* xg = x + ((size_t)b*Hh)*Ww*Cc + gi*Dd;
    float* og = out + ((size_t)b*Hh)*Ww*Cc + gi*Dd + ch0;

    // zero the two w-halo columns (cols 0 and 49)
    if (tid < 160) {
        int tr = tid >> 4, rest = tid & 15;
        int col = (rest < 8) ? 0 : 49;
        int cq = (rest & 7) * 4;
        *(float4*)&s_t[tr][col][cq] = make_float4(0.f,0.f,0.f,0.f);
    }
    // stage tile rows (zero-fill out-of-range rows)
    for (int i = tid; i < 10*384; i += 512) {
        int tr = i / 384, rem = i - tr*384;
        int w = rem >> 3, cq = (rem & 7) * 4;
        int hh = h0 - 1 + tr;
        float4 v = make_float4(0.f,0.f,0.f,0.f);
        if (hh >= 0 && hh < Hh)
            v = *(const float4*)(xg + ((size_t)hh*Ww + w)*Cc + cq);
        *(float4*)&s_t[tr][w+1][cq] = v;
    }
    // stage gates + weff
    if (tid < 256) s_gh[tid >> 5][tid & 31] = g_xh[(bg*Hh + h0 + (tid >> 5))*Dd + (tid & 31)];
    for (int i = tid; i < Ww*Dd; i += 512) s_gw[i >> 5][i & 31] = g_xw[bg*Ww*Dd + i];
    if (tid < 288) s_wk[tid >> 5][tid & 31] = g_weff[bg*9*Dd + tid];
    __syncthreads();

    float4 cv   = *(const float4*)&g_c[bg*Dd + ch0];
    float csum = g_csum[bg], cb = g_cb[bg], beff = g_beff[bg];

#pragma unroll
    for (int it = 0; it < 6; ++it) {
        int q = warp*24 + it*4 + sg;          // 0..383 pixel within band
        int hl = q / Ww, w = q - hl*Ww;       // hl 0..7

        float cx = 0.f, cy = 0.f, cz = 0.f, cw = 0.f;
        float4 gx;
#pragma unroll
        for (int dy = 0; dy < 3; ++dy) {
#pragma unroll
            for (int dx = 0; dx < 3; ++dx) {
                float4 v = *(const float4*)&s_t[hl + dy][w + dx][ch0];
                float4 wk = *(const float4*)&s_wk[dy*3 + dx][ch0];
                cx = fmaf(v.x, wk.x, cx);
                cy = fmaf(v.y, wk.y, cy);
                cz = fmaf(v.z, wk.z, cz);
                cw = fmaf(v.w, wk.w, cw);
                if (dy == 1 && dx == 1) gx = v;
            }
        }
        float conv = (cx + cy) + (cz + cw);

        float4 xh = *(const float4*)&s_gh[hl][ch0];
        float4 xw = *(const float4*)&s_gw[w][ch0];
        float4 y;
        y.x = gx.x*xh.x*xw.x; y.y = gx.y*xh.y*xw.y;
        y.z = gx.z*xh.z*xw.z; y.w = gx.w*xh.w*xw.w;
        float s1 = (y.x + y.y) + (y.z + y.w);
        float s2 = (y.x*y.x + y.y*y.y) + (y.z*y.z + y.w*y.w);
        float s3 = (cv.x*y.x + cv.y*y.y) + (cv.z*y.z + cv.w*y.w);
#pragma unroll
        for (int o = 4; o; o >>= 1) {
            conv += __shfl_xor_sync(0xffffffffu, conv, o);
            s1   += __shfl_xor_sync(0xffffffffu, s1,   o);
            s2   += __shfl_xor_sync(0xffffffffu, s2,   o);
            s3   += __shfl_xor_sync(0xffffffffu, s3,   o);
        }
        float w1  = conv + beff;
        float mu  = s1 * (1.f/Dd);
        float var = s2 * (1.f/Dd) - mu*mu;
        float rs  = rsqrtf(var + LN_EPS);
        float w2  = rs * (s3 - mu*csum) + cb;
        float gate = 1.f/(1.f + expf(-(w1 + w2)));

        float4 o4;
        o4.x = gx.x*gate; o4.y = gx.y*gate; o4.z = gx.z*gate; o4.w = gx.w*gate;
        *(float4*)(og + ((size_t)(h0 + hl)*Ww + w)*Cc) = o4;
    }
}

// ---------------------------------------------------------------------------
extern "C" void kernel_launch(void* const* d_in, const int* in_sizes, int n_in,
                              void* d_out, int out_size)
{
    const float* x   = (const float*)d_in[0];
    const float* w1  = (const float*)d_in[1];
    const float* b1  = (const float*)d_in[2];
    const float* w3  = (const float*)d_in[3];
    const float* b3  = (const float*)d_in[4];
    const float* gm  = (const float*)d_in[5];
    const float* bt  = (const float*)d_in[6];
    float* out = (float*)d_out;

    static int configured = 0;
    if (!configured) {
        cudaFuncSetAttribute(fused1234, cudaFuncAttributeMaxDynamicSharedMemorySize,
                             F_TOTAL * 4);
        cudaFuncSetAttribute(pass5, cudaFuncAttributeMaxDynamicSharedMemorySize,
                             P_TOTAL * 4);
        configured = 1;
    }

    fused1234<<<BG, 512, F_TOTAL*4>>>(x, w1, b1, w3, b3, gm, bt);
    pass5<<<BG*8, 512, P_TOTAL*4>>>(x, out);
}